// round 2
// baseline (speedup 1.0000x reference)
#include <cuda_runtime.h>
#include <cuda_bf16.h>
#include <cstdint>

#define N_  50000
#define E_  800000
#define G_  64

// ---------------- scratch (device globals; no allocation) ----------------
__device__ int   g_deg[N_];
__device__ int   g_rowptr[N_ + 1];
__device__ int   g_cursor[N_];
__device__ float g_dinv[N_];
__device__ int   g_csr_src[E_];
__device__ float g_csr_w[E_];

__device__ float g_h0[(size_t)N_ * 64];
__device__ float g_a1[(size_t)N_ * 64];
__device__ float g_h1[(size_t)N_ * 128];
__device__ float g_a2[(size_t)N_ * 128];
__device__ float g_h2[(size_t)N_ * 128];

__device__ float g_psum[G_ * 128];
__device__ float g_pmax[G_ * 128];
__device__ int   g_pcnt[G_];

// ---------------- zero / reset ----------------
__global__ void zero_kernel() {
    int i = blockIdx.x * blockDim.x + threadIdx.x;
    if (i < N_) g_deg[i] = 0;
    if (i < G_ * 128) { g_psum[i] = 0.f; g_pmax[i] = 0.f; }
    if (i < G_) g_pcnt[i] = 0;
}

// ---------------- degree count (edge_index is int32: JAX x64 disabled) ----------------
__global__ void count_kernel(const int* __restrict__ ei) {
    int e = blockIdx.x * blockDim.x + threadIdx.x;
    if (e >= E_) return;
    int d = ei[E_ + e];
    atomicAdd(&g_deg[d], 1);
}

// ---------------- single-block scan: rowptr, cursor, dinv ----------------
__global__ void scan_kernel() {
    __shared__ int sm[1024];
    __shared__ int carry_s;
    int t = threadIdx.x;
    if (t == 0) carry_s = 0;
    __syncthreads();
    for (int base = 0; base < N_; base += 1024) {
        int i = base + t;
        int v = (i < N_) ? g_deg[i] : 0;
        sm[t] = v;
        __syncthreads();
        for (int off = 1; off < 1024; off <<= 1) {
            int add = (t >= off) ? sm[t - off] : 0;
            __syncthreads();
            sm[t] += add;
            __syncthreads();
        }
        if (i < N_) {
            int excl = carry_s + sm[t] - v;
            g_rowptr[i] = excl;
            g_cursor[i] = excl;
            g_dinv[i]   = rsqrtf((float)(v + 1));   // +1 self loop
        }
        __syncthreads();
        if (t == 0) carry_s += sm[1023];
        __syncthreads();
    }
    if (t == 0) g_rowptr[N_] = carry_s;
}

// ---------------- CSR fill ----------------
__global__ void fill_kernel(const int* __restrict__ ei) {
    int e = blockIdx.x * blockDim.x + threadIdx.x;
    if (e >= E_) return;
    int s = ei[e];
    int d = ei[E_ + e];
    int pos = atomicAdd(&g_cursor[d], 1);
    g_csr_src[pos] = s;
    g_csr_w[pos]   = g_dinv[s];
}

// ---------------- input projection: h0 = x @ W_in + b_in  (K=6, 64 cols) ----------------
__global__ void gemm_in_kernel(const float* __restrict__ x,
                               const float* __restrict__ W,
                               const float* __restrict__ b) {
    __shared__ float Ws[6 * 64];
    __shared__ float bs[64];
    int t = threadIdx.x;               // 256 threads
    for (int i = t; i < 6 * 64; i += 256) Ws[i] = W[i];
    if (t < 64) bs[t] = b[t];
    __syncthreads();
    int row = blockIdx.x * 4 + (t >> 6);
    int col = t & 63;
    if (row >= N_) return;
    float acc = bs[col];
#pragma unroll
    for (int k = 0; k < 6; k++)
        acc += x[row * 6 + k] * Ws[k * 64 + col];
    g_h0[(size_t)row * 64 + col] = acc;
}

// ---------------- SpMM: out[i] = dinv[i]*( sum_e w_e * h[src_e] + dinv[i]*h[i] ) ----------------
template <int F>
__global__ void spmm_kernel(const float* __restrict__ hin, float* __restrict__ out) {
    int lane = threadIdx.x & 31;
    int warp = blockIdx.x * (blockDim.x >> 5) + (threadIdx.x >> 5);
    if (warp >= N_) return;
    int beg = g_rowptr[warp], end = g_rowptr[warp + 1];

    if constexpr (F == 128) {
        float4 acc = make_float4(0.f, 0.f, 0.f, 0.f);
        int e = beg;
        for (; e + 2 <= end; e += 2) {
            int s0 = g_csr_src[e];     float w0 = g_csr_w[e];
            int s1 = g_csr_src[e + 1]; float w1 = g_csr_w[e + 1];
            float4 v0 = ((const float4*)(hin + (size_t)s0 * 128))[lane];
            float4 v1 = ((const float4*)(hin + (size_t)s1 * 128))[lane];
            acc.x += w0 * v0.x + w1 * v1.x;
            acc.y += w0 * v0.y + w1 * v1.y;
            acc.z += w0 * v0.z + w1 * v1.z;
            acc.w += w0 * v0.w + w1 * v1.w;
        }
        if (e < end) {
            int s0 = g_csr_src[e]; float w0 = g_csr_w[e];
            float4 v0 = ((const float4*)(hin + (size_t)s0 * 128))[lane];
            acc.x += w0 * v0.x; acc.y += w0 * v0.y;
            acc.z += w0 * v0.z; acc.w += w0 * v0.w;
        }
        float di = g_dinv[warp];
        float4 hv = ((const float4*)(hin + (size_t)warp * 128))[lane];
        acc.x = di * (acc.x + di * hv.x);
        acc.y = di * (acc.y + di * hv.y);
        acc.z = di * (acc.z + di * hv.z);
        acc.w = di * (acc.w + di * hv.w);
        ((float4*)(out + (size_t)warp * 128))[lane] = acc;
    } else {  // F == 64
        float2 acc = make_float2(0.f, 0.f);
        int e = beg;
        for (; e + 2 <= end; e += 2) {
            int s0 = g_csr_src[e];     float w0 = g_csr_w[e];
            int s1 = g_csr_src[e + 1]; float w1 = g_csr_w[e + 1];
            float2 v0 = ((const float2*)(hin + (size_t)s0 * 64))[lane];
            float2 v1 = ((const float2*)(hin + (size_t)s1 * 64))[lane];
            acc.x += w0 * v0.x + w1 * v1.x;
            acc.y += w0 * v0.y + w1 * v1.y;
        }
        if (e < end) {
            int s0 = g_csr_src[e]; float w0 = g_csr_w[e];
            float2 v0 = ((const float2*)(hin + (size_t)s0 * 64))[lane];
            acc.x += w0 * v0.x; acc.y += w0 * v0.y;
        }
        float di = g_dinv[warp];
        float2 hv = ((const float2*)(hin + (size_t)warp * 64))[lane];
        acc.x = di * (acc.x + di * hv.x);
        acc.y = di * (acc.y + di * hv.y);
        ((float2*)(out + (size_t)warp * 64))[lane] = acc;
    }
}

// ---------------- dense GEMM: C[N,128] = relu(A[N,K] @ W[K,128] + b) ----------------
template <int K>
__global__ void __launch_bounds__(256) gemm_kernel(const float* __restrict__ A,
                                                   const float* __restrict__ W,
                                                   const float* __restrict__ b,
                                                   float* __restrict__ C) {
    __shared__ float Ws[64 * 128];     // 32 KB: one 64-row K-chunk of W
    __shared__ float As[64 * 64];      // 16 KB: 64 rows x 64 k-chunk of A
    int r0   = blockIdx.x * 64;
    int rowg = threadIdx.x >> 5;       // 0..7
    int lane = threadIdx.x & 31;
    int c    = lane * 4;

    float acc[8][4];
    float4 bv = *(const float4*)(b + c);
#pragma unroll
    for (int j = 0; j < 8; j++) { acc[j][0] = bv.x; acc[j][1] = bv.y; acc[j][2] = bv.z; acc[j][3] = bv.w; }

    for (int kb = 0; kb < K; kb += 64) {
        __syncthreads();
        // load W chunk (rows kb..kb+63 of [K,128]) -> 2048 float4, 8/thread
        const float4* Wg = (const float4*)(W + (size_t)kb * 128);
        float4* Wsv = (float4*)Ws;
#pragma unroll
        for (int i = 0; i < 8; i++)
            Wsv[threadIdx.x + i * 256] = Wg[threadIdx.x + i * 256];
        // load A chunk (64 rows x 64 cols) -> 1024 float4, 4/thread
#pragma unroll
        for (int i = 0; i < 4; i++) {
            int idx = threadIdx.x + i * 256;   // float4 index
            int r = idx >> 4;                  // 16 float4 per row
            int k4 = idx & 15;
            float4 v = make_float4(0.f, 0.f, 0.f, 0.f);
            if (r0 + r < N_)
                v = *(const float4*)(A + (size_t)(r0 + r) * K + kb + k4 * 4);
            *(float4*)&As[r * 64 + k4 * 4] = v;
        }
        __syncthreads();
#pragma unroll 4
        for (int k = 0; k < 64; k++) {
            float4 wv = *(const float4*)&Ws[k * 128 + c];
#pragma unroll
            for (int j = 0; j < 8; j++) {
                float a = As[(rowg + 8 * j) * 64 + k];
                acc[j][0] += a * wv.x;
                acc[j][1] += a * wv.y;
                acc[j][2] += a * wv.z;
                acc[j][3] += a * wv.w;
            }
        }
    }
#pragma unroll
    for (int j = 0; j < 8; j++) {
        int r = r0 + rowg + 8 * j;
        if (r < N_) {
            float4 o;
            o.x = fmaxf(acc[j][0], 0.f);
            o.y = fmaxf(acc[j][1], 0.f);
            o.z = fmaxf(acc[j][2], 0.f);
            o.w = fmaxf(acc[j][3], 0.f);
            *(float4*)(C + (size_t)r * 128 + c) = o;
        }
    }
}

// ---------------- pooling: per-graph mean-sum / max over sorted batch ----------------
__device__ __forceinline__ void pool_flush(int g, int lane, float4 s, float4 m, int cnt) {
    int base = g * 128 + lane * 4;
    atomicAdd(&g_psum[base + 0], s.x);
    atomicAdd(&g_psum[base + 1], s.y);
    atomicAdd(&g_psum[base + 2], s.z);
    atomicAdd(&g_psum[base + 3], s.w);
    atomicMax((int*)&g_pmax[base + 0], __float_as_int(m.x));
    atomicMax((int*)&g_pmax[base + 1], __float_as_int(m.y));
    atomicMax((int*)&g_pmax[base + 2], __float_as_int(m.z));
    atomicMax((int*)&g_pmax[base + 3], __float_as_int(m.w));
    if (lane == 0) atomicAdd(&g_pcnt[g], cnt);
}

__global__ void pool_kernel(const float* __restrict__ h, const int* __restrict__ batch) {
    int lane = threadIdx.x & 31;
    int warp = blockIdx.x * (blockDim.x >> 5) + (threadIdx.x >> 5);
    int n0 = warp * 64;
    if (n0 >= N_) return;
    int n1 = min(n0 + 64, N_);
    float4 s = make_float4(0.f, 0.f, 0.f, 0.f);
    float4 m = make_float4(0.f, 0.f, 0.f, 0.f);
    int cnt = 0;
    int cur = batch[n0];
    for (int n = n0; n < n1; n++) {
        int g = batch[n];
        if (g != cur) {
            pool_flush(cur, lane, s, m, cnt);
            s = make_float4(0.f, 0.f, 0.f, 0.f);
            m = make_float4(0.f, 0.f, 0.f, 0.f);
            cnt = 0; cur = g;
        }
        float4 v = ((const float4*)(h + (size_t)n * 128))[lane];
        s.x += v.x; s.y += v.y; s.z += v.z; s.w += v.w;
        m.x = fmaxf(m.x, v.x); m.y = fmaxf(m.y, v.y);
        m.z = fmaxf(m.z, v.z); m.w = fmaxf(m.w, v.w);
        cnt++;
    }
    pool_flush(cur, lane, s, m, cnt);
}

// ---------------- final MLP: out = relu([mean|max] @ Wp + bp) ----------------
__global__ void mlp_kernel(const float* __restrict__ Wp, const float* __restrict__ bp,
                           float* __restrict__ out) {
    __shared__ float hg[256];
    int g = blockIdx.x;
    int t = threadIdx.x;   // 256
    if (t < 128) {
        float cnt = (float)max(g_pcnt[g], 1);
        hg[t] = g_psum[g * 128 + t] / cnt;
    } else {
        hg[t] = g_pmax[g * 128 + (t - 128)];
    }
    __syncthreads();
    float acc = bp[t];
#pragma unroll 8
    for (int k = 0; k < 256; k++)
        acc += hg[k] * Wp[k * 256 + t];
    out[g * 256 + t] = fmaxf(acc, 0.f);
}

// ---------------- launch ----------------
extern "C" void kernel_launch(void* const* d_in, const int* in_sizes, int n_in,
                              void* d_out, int out_size) {
    const float* x     = (const float*)d_in[0];
    const int*   ei    = (const int*)d_in[1];     // int32 (JAX x64 disabled)
    const int*   batch = (const int*)d_in[2];     // int32
    const float* W_in  = (const float*)d_in[3];
    const float* b_in  = (const float*)d_in[4];
    const float* W1    = (const float*)d_in[5];
    const float* b1    = (const float*)d_in[6];
    const float* W2    = (const float*)d_in[7];
    const float* b2    = (const float*)d_in[8];
    const float* Wp    = (const float*)d_in[9];
    const float* bp    = (const float*)d_in[10];
    float* out = (float*)d_out;

    float *h0p, *a1p, *h1p, *a2p, *h2p;
    cudaGetSymbolAddress((void**)&h0p, g_h0);
    cudaGetSymbolAddress((void**)&a1p, g_a1);
    cudaGetSymbolAddress((void**)&h1p, g_h1);
    cudaGetSymbolAddress((void**)&a2p, g_a2);
    cudaGetSymbolAddress((void**)&h2p, g_h2);

    zero_kernel<<<(N_ + 255) / 256, 256>>>();
    count_kernel<<<(E_ + 255) / 256, 256>>>(ei);
    scan_kernel<<<1, 1024>>>();
    fill_kernel<<<(E_ + 255) / 256, 256>>>(ei);

    gemm_in_kernel<<<(N_ + 3) / 4, 256>>>(x, W_in, b_in);

    // layer 1: aggregate (64-dim) then GEMM+relu
    spmm_kernel<64><<<(N_ + 7) / 8, 256>>>(h0p, a1p);
    gemm_kernel<64><<<(N_ + 63) / 64, 256>>>(a1p, W1, b1, h1p);

    // layer 2: aggregate (128-dim) then GEMM+relu
    spmm_kernel<128><<<(N_ + 7) / 8, 256>>>(h1p, a2p);
    gemm_kernel<128><<<(N_ + 63) / 64, 256>>>(a2p, W2, b2, h2p);

    // pooling (warp per 64-node chunk)
    {
        int warps = (N_ + 63) / 64;
        int blocks = (warps * 32 + 255) / 256;
        pool_kernel<<<blocks, 256>>>(h2p, batch);
    }

    mlp_kernel<<<G_, 256>>>(Wp, bp, out);
}

// round 3
// speedup vs baseline: 1.4054x; 1.4054x over previous
#include <cuda_runtime.h>
#include <cuda_bf16.h>
#include <cstdint>

#define N_  50000
#define E_  800000
#define G_  64

// ---------------- scratch (device globals; no allocation) ----------------
__device__ int   g_deg[N_];
__device__ int   g_rowptr[N_ + 1];
__device__ int   g_cursor[N_];
__device__ float g_dinv[N_];
__device__ int   g_csr_src[E_];

__device__ int   g_scan[50176];        // 98 blocks * 512
__device__ int   g_bsum[128];
__device__ int   g_boff[128];

__device__ float g_Wc[6 * 128];        // W_in @ W1
__device__ float g_bW[128];            // b_in @ W1
__device__ float g_ax[(size_t)N_ * 6]; // agg6(x)
__device__ float g_s[N_];              // normalized self+neighbor weight sum

__device__ float g_h1[(size_t)N_ * 128];
__device__ float g_a2[(size_t)N_ * 128];
__device__ float g_h2[(size_t)N_ * 128];

__device__ float g_psum[G_ * 128];
__device__ float g_pmax[G_ * 128];
__device__ int   g_pcnt[G_];

// ---------------- zero / reset ----------------
__global__ void zero_kernel() {
    int i = blockIdx.x * blockDim.x + threadIdx.x;
    if (i < N_) g_deg[i] = 0;
    if (i < G_ * 128) { g_psum[i] = 0.f; g_pmax[i] = 0.f; }
    if (i < G_) g_pcnt[i] = 0;
    if (i == 0) g_rowptr[N_] = E_;
}

// ---------------- degree count (int4-vectorized dst reads) ----------------
__global__ void count_kernel(const int* __restrict__ ei) {
    int e4 = blockIdx.x * blockDim.x + threadIdx.x;
    if (e4 * 4 >= E_) return;
    int4 d = ((const int4*)(ei + E_))[e4];
    atomicAdd(&g_deg[d.x], 1);
    atomicAdd(&g_deg[d.y], 1);
    atomicAdd(&g_deg[d.z], 1);
    atomicAdd(&g_deg[d.w], 1);
}

// ---------------- scan stage 1: per-block inclusive scan + dinv ----------------
__global__ void __launch_bounds__(512) scan1_kernel() {
    __shared__ int wsum[16];
    int t = threadIdx.x, lane = t & 31, wid = t >> 5;
    int i = blockIdx.x * 512 + t;
    int v = (i < N_) ? g_deg[i] : 0;
    int incl = v;
#pragma unroll
    for (int off = 1; off < 32; off <<= 1) {
        int n = __shfl_up_sync(0xffffffffu, incl, off);
        if (lane >= off) incl += n;
    }
    if (lane == 31) wsum[wid] = incl;
    __syncthreads();
    if (wid == 0) {
        int s = (lane < 16) ? wsum[lane] : 0;
#pragma unroll
        for (int off = 1; off < 16; off <<= 1) {
            int n = __shfl_up_sync(0xffffffffu, s, off);
            if (lane >= off) s += n;
        }
        if (lane < 16) wsum[lane] = s;
    }
    __syncthreads();
    if (wid > 0) incl += wsum[wid - 1];
    g_scan[blockIdx.x * 512 + t] = incl;
    if (t == 511) g_bsum[blockIdx.x] = incl;
    if (i < N_) g_dinv[i] = rsqrtf((float)(v + 1));   // +1 self loop
}

// ---------------- scan stage 2: block-partial exclusive scan (98 values) ----------------
__global__ void scan2_kernel(int nblk) {
    __shared__ int sm[128];
    int t = threadIdx.x;
    int v = (t < nblk) ? g_bsum[t] : 0;
    sm[t] = v;
    __syncthreads();
    for (int off = 1; off < 128; off <<= 1) {
        int add = (t >= off) ? sm[t - off] : 0;
        __syncthreads();
        sm[t] += add;
        __syncthreads();
    }
    if (t < nblk) g_boff[t] = sm[t] - v;   // exclusive
}

// ---------------- scan stage 3: rowptr / cursor ----------------
__global__ void scan3_kernel() {
    int i = blockIdx.x * blockDim.x + threadIdx.x;
    if (i >= N_) return;
    int excl = g_boff[i >> 9] + g_scan[i] - g_deg[i];
    g_rowptr[i] = excl;
    g_cursor[i] = excl;
}

// ---------------- CSR fill (src only; 4 edges/thread) ----------------
__global__ void fill_kernel(const int* __restrict__ ei) {
    int e4 = blockIdx.x * blockDim.x + threadIdx.x;
    if (e4 * 4 >= E_) return;
    int4 s = ((const int4*)ei)[e4];
    int4 d = ((const int4*)(ei + E_))[e4];
    g_csr_src[atomicAdd(&g_cursor[d.x], 1)] = s.x;
    g_csr_src[atomicAdd(&g_cursor[d.y], 1)] = s.y;
    g_csr_src[atomicAdd(&g_cursor[d.z], 1)] = s.z;
    g_csr_src[atomicAdd(&g_cursor[d.w], 1)] = s.w;
}

// ---------------- prep: W_c = W_in @ W1 [6,128], bW = b_in @ W1 [128] ----------------
__global__ void prep_kernel(const float* __restrict__ W_in,
                            const float* __restrict__ b_in,
                            const float* __restrict__ W1) {
    int c = threadIdx.x;   // 128
    float acc[6] = {0.f, 0.f, 0.f, 0.f, 0.f, 0.f};
    float bb = 0.f;
    for (int k = 0; k < 64; k++) {
        float w1 = W1[k * 128 + c];
        bb += b_in[k] * w1;
#pragma unroll
        for (int r = 0; r < 6; r++)
            acc[r] += W_in[r * 64 + k] * w1;
    }
#pragma unroll
    for (int r = 0; r < 6; r++)
        g_Wc[r * 128 + c] = acc[r];
    g_bW[c] = bb;
}

// ---------------- spmm6: aggregate raw 6-dim features + weight-sum s ----------------
__global__ void spmm6_kernel(const float* __restrict__ x) {
    int lane = threadIdx.x & 31;
    int node = blockIdx.x * (blockDim.x >> 5) + (threadIdx.x >> 5);
    if (node >= N_) return;
    int beg = g_rowptr[node], end = g_rowptr[node + 1];

    float a0 = 0.f, a1 = 0.f, a2 = 0.f, a3 = 0.f, a4 = 0.f, a5 = 0.f, ws = 0.f;
    for (int e = beg + lane; e < end; e += 32) {
        int s = g_csr_src[e];
        float w = g_dinv[s];
        const float2* xr = (const float2*)(x + (size_t)s * 6);
        float2 p0 = xr[0], p1 = xr[1], p2 = xr[2];
        a0 += w * p0.x; a1 += w * p0.y;
        a2 += w * p1.x; a3 += w * p1.y;
        a4 += w * p2.x; a5 += w * p2.y;
        ws += w;
    }
#pragma unroll
    for (int off = 16; off; off >>= 1) {
        a0 += __shfl_down_sync(0xffffffffu, a0, off);
        a1 += __shfl_down_sync(0xffffffffu, a1, off);
        a2 += __shfl_down_sync(0xffffffffu, a2, off);
        a3 += __shfl_down_sync(0xffffffffu, a3, off);
        a4 += __shfl_down_sync(0xffffffffu, a4, off);
        a5 += __shfl_down_sync(0xffffffffu, a5, off);
        ws += __shfl_down_sync(0xffffffffu, ws, off);
    }
    if (lane == 0) {
        float di = g_dinv[node];
        const float2* xi = (const float2*)(x + (size_t)node * 6);
        float2 q0 = xi[0], q1 = xi[1], q2 = xi[2];
        float* o = g_ax + (size_t)node * 6;
        o[0] = di * (a0 + di * q0.x);
        o[1] = di * (a1 + di * q0.y);
        o[2] = di * (a2 + di * q1.x);
        o[3] = di * (a3 + di * q1.y);
        o[4] = di * (a4 + di * q2.x);
        o[5] = di * (a5 + di * q2.y);
        g_s[node] = di * (ws + di);
    }
}

// ---------------- layer1: h1 = relu(ax @ Wc + s*bW + b1) ----------------
__global__ void __launch_bounds__(256) layer1_kernel(const float* __restrict__ b1) {
    __shared__ float Wcs[6 * 128];
    __shared__ float bWs[128];
    __shared__ float b1s[128];
    __shared__ float axs[32 * 6];
    __shared__ float ss[32];
    int t = threadIdx.x;
    int r0 = blockIdx.x * 32;

    for (int i = t; i < 6 * 128; i += 256) Wcs[i] = g_Wc[i];
    if (t < 128) { bWs[t] = g_bW[t]; b1s[t] = b1[t]; }
    if (t < 192) {
        int idx = r0 * 6 + t;
        axs[t] = (idx < N_ * 6) ? g_ax[idx] : 0.f;
    }
    if (t >= 192 && t < 224) {
        int r = r0 + (t - 192);
        ss[t - 192] = (r < N_) ? g_s[r] : 0.f;
    }
    __syncthreads();

    int col = t & 127;
    int rl0 = t >> 7;   // 0 or 1
#pragma unroll
    for (int j = 0; j < 16; j++) {
        int rl = rl0 + 2 * j;
        int row = r0 + rl;
        if (row >= N_) break;
        float acc = ss[rl] * bWs[col] + b1s[col];
#pragma unroll
        for (int k = 0; k < 6; k++)
            acc += axs[rl * 6 + k] * Wcs[k * 128 + col];
        g_h1[(size_t)row * 128 + col] = fmaxf(acc, 0.f);
    }
}

// ---------------- spmm128: a2[i] = dinv_i*( sum w_e*h1[src] + dinv_i*h1[i] ) ----------------
__global__ void spmm128_kernel(const float* __restrict__ hin, float* __restrict__ out) {
    int lane = threadIdx.x & 31;
    int node = blockIdx.x * (blockDim.x >> 5) + (threadIdx.x >> 5);
    if (node >= N_) return;
    int beg = g_rowptr[node], end = g_rowptr[node + 1];

    float4 acc = make_float4(0.f, 0.f, 0.f, 0.f);
    int e = beg;
    for (; e + 2 <= end; e += 2) {
        int s0 = g_csr_src[e];
        int s1 = g_csr_src[e + 1];
        float w0 = g_dinv[s0];
        float w1 = g_dinv[s1];
        float4 v0 = ((const float4*)(hin + (size_t)s0 * 128))[lane];
        float4 v1 = ((const float4*)(hin + (size_t)s1 * 128))[lane];
        acc.x += w0 * v0.x + w1 * v1.x;
        acc.y += w0 * v0.y + w1 * v1.y;
        acc.z += w0 * v0.z + w1 * v1.z;
        acc.w += w0 * v0.w + w1 * v1.w;
    }
    if (e < end) {
        int s0 = g_csr_src[e];
        float w0 = g_dinv[s0];
        float4 v0 = ((const float4*)(hin + (size_t)s0 * 128))[lane];
        acc.x += w0 * v0.x; acc.y += w0 * v0.y;
        acc.z += w0 * v0.z; acc.w += w0 * v0.w;
    }
    float di = g_dinv[node];
    float4 hv = ((const float4*)(hin + (size_t)node * 128))[lane];
    acc.x = di * (acc.x + di * hv.x);
    acc.y = di * (acc.y + di * hv.y);
    acc.z = di * (acc.z + di * hv.z);
    acc.w = di * (acc.w + di * hv.w);
    ((float4*)(out + (size_t)node * 128))[lane] = acc;
}

// ---------------- dense GEMM: C[N,128] = relu(A[N,128] @ W[128,128] + b) ----------------
__global__ void __launch_bounds__(256) gemm128_kernel(const float* __restrict__ A,
                                                      const float* __restrict__ W,
                                                      const float* __restrict__ b,
                                                      float* __restrict__ C) {
    __shared__ float Ws[64 * 128];
    __shared__ float As[64 * 64];
    const int K = 128;
    int r0   = blockIdx.x * 64;
    int rowg = threadIdx.x >> 5;
    int lane = threadIdx.x & 31;
    int c    = lane * 4;

    float acc[8][4];
    float4 bv = *(const float4*)(b + c);
#pragma unroll
    for (int j = 0; j < 8; j++) { acc[j][0] = bv.x; acc[j][1] = bv.y; acc[j][2] = bv.z; acc[j][3] = bv.w; }

    for (int kb = 0; kb < K; kb += 64) {
        __syncthreads();
        const float4* Wg = (const float4*)(W + (size_t)kb * 128);
        float4* Wsv = (float4*)Ws;
#pragma unroll
        for (int i = 0; i < 8; i++)
            Wsv[threadIdx.x + i * 256] = Wg[threadIdx.x + i * 256];
#pragma unroll
        for (int i = 0; i < 4; i++) {
            int idx = threadIdx.x + i * 256;
            int r = idx >> 4;
            int k4 = idx & 15;
            float4 v = make_float4(0.f, 0.f, 0.f, 0.f);
            if (r0 + r < N_)
                v = *(const float4*)(A + (size_t)(r0 + r) * K + kb + k4 * 4);
            *(float4*)&As[r * 64 + k4 * 4] = v;
        }
        __syncthreads();
#pragma unroll 4
        for (int k = 0; k < 64; k++) {
            float4 wv = *(const float4*)&Ws[k * 128 + c];
#pragma unroll
            for (int j = 0; j < 8; j++) {
                float a = As[(rowg + 8 * j) * 64 + k];
                acc[j][0] += a * wv.x;
                acc[j][1] += a * wv.y;
                acc[j][2] += a * wv.z;
                acc[j][3] += a * wv.w;
            }
        }
    }
#pragma unroll
    for (int j = 0; j < 8; j++) {
        int r = r0 + rowg + 8 * j;
        if (r < N_) {
            float4 o;
            o.x = fmaxf(acc[j][0], 0.f);
            o.y = fmaxf(acc[j][1], 0.f);
            o.z = fmaxf(acc[j][2], 0.f);
            o.w = fmaxf(acc[j][3], 0.f);
            *(float4*)(C + (size_t)r * 128 + c) = o;
        }
    }
}

// ---------------- pooling ----------------
__device__ __forceinline__ void pool_flush(int g, int lane, float4 s, float4 m, int cnt) {
    int base = g * 128 + lane * 4;
    atomicAdd(&g_psum[base + 0], s.x);
    atomicAdd(&g_psum[base + 1], s.y);
    atomicAdd(&g_psum[base + 2], s.z);
    atomicAdd(&g_psum[base + 3], s.w);
    atomicMax((int*)&g_pmax[base + 0], __float_as_int(m.x));
    atomicMax((int*)&g_pmax[base + 1], __float_as_int(m.y));
    atomicMax((int*)&g_pmax[base + 2], __float_as_int(m.z));
    atomicMax((int*)&g_pmax[base + 3], __float_as_int(m.w));
    if (lane == 0) atomicAdd(&g_pcnt[g], cnt);
}

__global__ void pool_kernel(const float* __restrict__ h, const int* __restrict__ batch) {
    int lane = threadIdx.x & 31;
    int warp = blockIdx.x * (blockDim.x >> 5) + (threadIdx.x >> 5);
    int n0 = warp * 64;
    if (n0 >= N_) return;
    int n1 = min(n0 + 64, N_);
    float4 s = make_float4(0.f, 0.f, 0.f, 0.f);
    float4 m = make_float4(0.f, 0.f, 0.f, 0.f);
    int cnt = 0;
    int cur = batch[n0];
    for (int n = n0; n < n1; n++) {
        int g = batch[n];
        if (g != cur) {
            pool_flush(cur, lane, s, m, cnt);
            s = make_float4(0.f, 0.f, 0.f, 0.f);
            m = make_float4(0.f, 0.f, 0.f, 0.f);
            cnt = 0; cur = g;
        }
        float4 v = ((const float4*)(h + (size_t)n * 128))[lane];
        s.x += v.x; s.y += v.y; s.z += v.z; s.w += v.w;
        m.x = fmaxf(m.x, v.x); m.y = fmaxf(m.y, v.y);
        m.z = fmaxf(m.z, v.z); m.w = fmaxf(m.w, v.w);
        cnt++;
    }
    pool_flush(cur, lane, s, m, cnt);
}

// ---------------- final MLP ----------------
__global__ void mlp_kernel(const float* __restrict__ Wp, const float* __restrict__ bp,
                           float* __restrict__ out) {
    __shared__ float hg[256];
    int g = blockIdx.x;
    int t = threadIdx.x;
    if (t < 128) {
        float cnt = (float)max(g_pcnt[g], 1);
        hg[t] = g_psum[g * 128 + t] / cnt;
    } else {
        hg[t] = g_pmax[g * 128 + (t - 128)];
    }
    __syncthreads();
    float acc = bp[t];
#pragma unroll 8
    for (int k = 0; k < 256; k++)
        acc += hg[k] * Wp[k * 256 + t];
    out[g * 256 + t] = fmaxf(acc, 0.f);
}

// ---------------- launch ----------------
extern "C" void kernel_launch(void* const* d_in, const int* in_sizes, int n_in,
                              void* d_out, int out_size) {
    const float* x     = (const float*)d_in[0];
    const int*   ei    = (const int*)d_in[1];
    const int*   batch = (const int*)d_in[2];
    const float* W_in  = (const float*)d_in[3];
    const float* b_in  = (const float*)d_in[4];
    const float* W1    = (const float*)d_in[5];
    const float* b1    = (const float*)d_in[6];
    const float* W2    = (const float*)d_in[7];
    const float* b2    = (const float*)d_in[8];
    const float* Wp    = (const float*)d_in[9];
    const float* bp    = (const float*)d_in[10];
    float* out = (float*)d_out;

    float *h1p, *a2p, *h2p;
    cudaGetSymbolAddress((void**)&h1p, g_h1);
    cudaGetSymbolAddress((void**)&a2p, g_a2);
    cudaGetSymbolAddress((void**)&h2p, g_h2);

    const int SCAN_BLOCKS = (N_ + 511) / 512;   // 98

    zero_kernel<<<(N_ + 255) / 256, 256>>>();
    count_kernel<<<(E_ / 4 + 255) / 256, 256>>>(ei);
    scan1_kernel<<<SCAN_BLOCKS, 512>>>();
    scan2_kernel<<<1, 128>>>(SCAN_BLOCKS);
    scan3_kernel<<<(N_ + 255) / 256, 256>>>();
    fill_kernel<<<(E_ / 4 + 255) / 256, 256>>>(ei);

    prep_kernel<<<1, 128>>>(W_in, b_in, W1);

    // layer 1: aggregate at 6 dims, then fused tiny GEMM
    spmm6_kernel<<<(N_ * 32 + 255) / 256, 256>>>(x);
    layer1_kernel<<<(N_ + 31) / 32, 256>>>(b1);

    // layer 2
    spmm128_kernel<<<(N_ + 7) / 8, 256>>>(h1p, a2p);
    gemm128_kernel<<<(N_ + 63) / 64, 256>>>(a2p, W2, b2, h2p);

    // pooling + MLP
    {
        int warps = (N_ + 63) / 64;
        int blocks = (warps * 32 + 255) / 256;
        pool_kernel<<<blocks, 256>>>(h2p, batch);
    }
    mlp_kernel<<<G_, 256>>>(Wp, bp, out);
}

// round 4
// speedup vs baseline: 1.4523x; 1.0333x over previous
#include <cuda_runtime.h>
#include <cuda_fp16.h>
#include <cstdint>

#define N_  50000
#define E_  800000
#define G_  64

// ---------------- scratch (device globals; no allocation) ----------------
__device__ int    g_deg[N_];
__device__ int    g_rowptr[N_ + 1];
__device__ int    g_cursor[N_];
__device__ float  g_dinv[N_];
__device__ int    g_csr_src[E_];

__device__ int    g_scan[50176];        // 98 blocks * 512
__device__ int    g_bsum[128];

__device__ float  g_Wc[6 * 128];        // W_in @ W1
__device__ float  g_bW[128];            // b_in @ W1

__device__ __half g_h1h[(size_t)N_ * 128];   // fp16 h1 (gather payload)
__device__ float  g_a2[(size_t)N_ * 128];
__device__ float  g_h2[(size_t)N_ * 128];

__device__ float  g_psum[G_ * 128];
__device__ float  g_pmax[G_ * 128];
__device__ int    g_pcnt[G_];

// ---------------- zero / reset ----------------
__global__ void zero_kernel() {
    int i = blockIdx.x * blockDim.x + threadIdx.x;
    if (i < N_) g_deg[i] = 0;
    if (i < G_ * 128) { g_psum[i] = 0.f; g_pmax[i] = 0.f; }
    if (i < G_) g_pcnt[i] = 0;
    if (i == 0) g_rowptr[N_] = E_;
}

// ---------------- degree count (int4-vectorized dst reads) ----------------
__global__ void count_kernel(const int* __restrict__ ei) {
    int e4 = blockIdx.x * blockDim.x + threadIdx.x;
    if (e4 * 4 >= E_) return;
    int4 d = ((const int4*)(ei + E_))[e4];
    atomicAdd(&g_deg[d.x], 1);
    atomicAdd(&g_deg[d.y], 1);
    atomicAdd(&g_deg[d.z], 1);
    atomicAdd(&g_deg[d.w], 1);
}

// ---------------- scan stage 1: per-block inclusive scan + dinv ----------------
__global__ void __launch_bounds__(512) scan1_kernel() {
    __shared__ int wsum[16];
    int t = threadIdx.x, lane = t & 31, wid = t >> 5;
    int i = blockIdx.x * 512 + t;
    int v = (i < N_) ? g_deg[i] : 0;
    int incl = v;
#pragma unroll
    for (int off = 1; off < 32; off <<= 1) {
        int n = __shfl_up_sync(0xffffffffu, incl, off);
        if (lane >= off) incl += n;
    }
    if (lane == 31) wsum[wid] = incl;
    __syncthreads();
    if (wid == 0) {
        int s = (lane < 16) ? wsum[lane] : 0;
#pragma unroll
        for (int off = 1; off < 16; off <<= 1) {
            int n = __shfl_up_sync(0xffffffffu, s, off);
            if (lane >= off) s += n;
        }
        if (lane < 16) wsum[lane] = s;
    }
    __syncthreads();
    if (wid > 0) incl += wsum[wid - 1];
    g_scan[blockIdx.x * 512 + t] = incl;
    if (t == 511) g_bsum[blockIdx.x] = incl;
    if (i < N_) g_dinv[i] = rsqrtf((float)(v + 1));   // +1 self loop
}

// ---------------- scan stage 2+3 merged: each block re-scans block sums ----------------
__global__ void scan23_kernel(int nblk) {
    __shared__ int sm[128];
    int t = threadIdx.x;   // 256
    if (t < 128) sm[t] = (t < nblk) ? g_bsum[t] : 0;
    __syncthreads();
    for (int off = 1; off < 128; off <<= 1) {
        int add = (t >= off && t < 128) ? sm[t - off] : 0;
        __syncthreads();
        if (t < 128) sm[t] += add;
        __syncthreads();
    }
    int i = blockIdx.x * 256 + t;
    if (i < N_) {
        int blk = i >> 9;
        int boff = blk ? sm[blk - 1] : 0;
        int excl = boff + g_scan[i] - g_deg[i];
        g_rowptr[i] = excl;
        g_cursor[i] = excl;
    }
}

// ---------------- CSR fill (src only; 4 edges/thread) ----------------
__global__ void fill_kernel(const int* __restrict__ ei) {
    int e4 = blockIdx.x * blockDim.x + threadIdx.x;
    if (e4 * 4 >= E_) return;
    int4 s = ((const int4*)ei)[e4];
    int4 d = ((const int4*)(ei + E_))[e4];
    g_csr_src[atomicAdd(&g_cursor[d.x], 1)] = s.x;
    g_csr_src[atomicAdd(&g_cursor[d.y], 1)] = s.y;
    g_csr_src[atomicAdd(&g_cursor[d.z], 1)] = s.z;
    g_csr_src[atomicAdd(&g_cursor[d.w], 1)] = s.w;
}

// ---------------- prep: W_c = W_in @ W1 [6,128], bW = b_in @ W1 [128] ----------------
__global__ void prep_kernel(const float* __restrict__ W_in,
                            const float* __restrict__ b_in,
                            const float* __restrict__ W1) {
    int c = threadIdx.x;   // 128
    float acc[6] = {0.f, 0.f, 0.f, 0.f, 0.f, 0.f};
    float bb = 0.f;
    for (int k = 0; k < 64; k++) {
        float w1 = W1[k * 128 + c];
        bb += b_in[k] * w1;
#pragma unroll
        for (int r = 0; r < 6; r++)
            acc[r] += W_in[r * 64 + k] * w1;
    }
#pragma unroll
    for (int r = 0; r < 6; r++)
        g_Wc[r * 128 + c] = acc[r];
    g_bW[c] = bb;
}

// ---------------- fused layer1: aggregate 6-dim + tiny GEMM + relu -> fp16 h1 ----------------
__global__ void __launch_bounds__(256) layer1_fused_kernel(const float* __restrict__ x,
                                                           const float* __restrict__ b1) {
    __shared__ float Wcs[6 * 128];
    __shared__ float bWs[128];
    __shared__ float b1s[128];
    int t = threadIdx.x;
    for (int i = t; i < 6 * 128; i += 256) Wcs[i] = g_Wc[i];
    if (t < 128) { bWs[t] = g_bW[t]; b1s[t] = b1[t]; }
    __syncthreads();

    int lane = t & 31;
    int node = blockIdx.x * 8 + (t >> 5);
    if (node >= N_) return;
    int beg = g_rowptr[node], end = g_rowptr[node + 1];

    float a0 = 0.f, a1 = 0.f, a2 = 0.f, a3 = 0.f, a4 = 0.f, a5 = 0.f, ws = 0.f;
    for (int e = beg + lane; e < end; e += 32) {
        int s = g_csr_src[e];
        float w = g_dinv[s];
        const float2* xr = (const float2*)(x + (size_t)s * 6);
        float2 p0 = xr[0], p1 = xr[1], p2 = xr[2];
        a0 += w * p0.x; a1 += w * p0.y;
        a2 += w * p1.x; a3 += w * p1.y;
        a4 += w * p2.x; a5 += w * p2.y;
        ws += w;
    }
    // butterfly reduce so every lane holds the full sums
#pragma unroll
    for (int off = 16; off; off >>= 1) {
        a0 += __shfl_xor_sync(0xffffffffu, a0, off);
        a1 += __shfl_xor_sync(0xffffffffu, a1, off);
        a2 += __shfl_xor_sync(0xffffffffu, a2, off);
        a3 += __shfl_xor_sync(0xffffffffu, a3, off);
        a4 += __shfl_xor_sync(0xffffffffu, a4, off);
        a5 += __shfl_xor_sync(0xffffffffu, a5, off);
        ws += __shfl_xor_sync(0xffffffffu, ws, off);
    }
    float di = g_dinv[node];
    const float2* xi = (const float2*)(x + (size_t)node * 6);
    float2 q0 = xi[0], q1 = xi[1], q2 = xi[2];
    float ax0 = di * (a0 + di * q0.x);
    float ax1 = di * (a1 + di * q0.y);
    float ax2 = di * (a2 + di * q1.x);
    float ax3 = di * (a3 + di * q1.y);
    float ax4 = di * (a4 + di * q2.x);
    float ax5 = di * (a5 + di * q2.y);
    float s   = di * (ws + di);

    int c = lane * 4;
    float o[4];
#pragma unroll
    for (int j = 0; j < 4; j++) {
        float acc = s * bWs[c + j] + b1s[c + j];
        acc += ax0 * Wcs[0 * 128 + c + j];
        acc += ax1 * Wcs[1 * 128 + c + j];
        acc += ax2 * Wcs[2 * 128 + c + j];
        acc += ax3 * Wcs[3 * 128 + c + j];
        acc += ax4 * Wcs[4 * 128 + c + j];
        acc += ax5 * Wcs[5 * 128 + c + j];
        o[j] = fmaxf(acc, 0.f);
    }
    __half2 h01 = __floats2half2_rn(o[0], o[1]);
    __half2 h23 = __floats2half2_rn(o[2], o[3]);
    uint2 u;
    u.x = *(unsigned int*)&h01;
    u.y = *(unsigned int*)&h23;
    ((uint2*)(g_h1h + (size_t)node * 128))[lane] = u;
}

// ---------------- spmm128 (fp16 gather): a2[i] = dinv_i*( sum w_e*h1[src] + dinv_i*h1[i] ) ----------------
__global__ void spmm128_kernel(float* __restrict__ out) {
    int lane = threadIdx.x & 31;
    int node = blockIdx.x * (blockDim.x >> 5) + (threadIdx.x >> 5);
    if (node >= N_) return;
    int beg = g_rowptr[node], end = g_rowptr[node + 1];

    float4 acc = make_float4(0.f, 0.f, 0.f, 0.f);
    int e = beg;
    for (; e + 2 <= end; e += 2) {
        int s0 = g_csr_src[e];
        int s1 = g_csr_src[e + 1];
        float w0 = g_dinv[s0];
        float w1 = g_dinv[s1];
        uint2 u0 = ((const uint2*)(g_h1h + (size_t)s0 * 128))[lane];
        uint2 u1 = ((const uint2*)(g_h1h + (size_t)s1 * 128))[lane];
        float2 f0a = __half22float2(*(__half2*)&u0.x);
        float2 f0b = __half22float2(*(__half2*)&u0.y);
        float2 f1a = __half22float2(*(__half2*)&u1.x);
        float2 f1b = __half22float2(*(__half2*)&u1.y);
        acc.x += w0 * f0a.x + w1 * f1a.x;
        acc.y += w0 * f0a.y + w1 * f1a.y;
        acc.z += w0 * f0b.x + w1 * f1b.x;
        acc.w += w0 * f0b.y + w1 * f1b.y;
    }
    if (e < end) {
        int s0 = g_csr_src[e];
        float w0 = g_dinv[s0];
        uint2 u0 = ((const uint2*)(g_h1h + (size_t)s0 * 128))[lane];
        float2 f0a = __half22float2(*(__half2*)&u0.x);
        float2 f0b = __half22float2(*(__half2*)&u0.y);
        acc.x += w0 * f0a.x; acc.y += w0 * f0a.y;
        acc.z += w0 * f0b.x; acc.w += w0 * f0b.y;
    }
    float di = g_dinv[node];
    uint2 us = ((const uint2*)(g_h1h + (size_t)node * 128))[lane];
    float2 fsa = __half22float2(*(__half2*)&us.x);
    float2 fsb = __half22float2(*(__half2*)&us.y);
    acc.x = di * (acc.x + di * fsa.x);
    acc.y = di * (acc.y + di * fsa.y);
    acc.z = di * (acc.z + di * fsb.x);
    acc.w = di * (acc.w + di * fsb.y);
    ((float4*)(out + (size_t)node * 128))[lane] = acc;
}

// ---------------- dense GEMM: C[N,128] = relu(A[N,128] @ W[128,128] + b) ----------------
__global__ void __launch_bounds__(256) gemm128_kernel(const float* __restrict__ A,
                                                      const float* __restrict__ W,
                                                      const float* __restrict__ b,
                                                      float* __restrict__ C) {
    __shared__ float Ws[64 * 128];
    __shared__ float As[64 * 64];
    const int K = 128;
    int r0   = blockIdx.x * 64;
    int rowg = threadIdx.x >> 5;
    int lane = threadIdx.x & 31;
    int c    = lane * 4;

    float acc[8][4];
    float4 bv = *(const float4*)(b + c);
#pragma unroll
    for (int j = 0; j < 8; j++) { acc[j][0] = bv.x; acc[j][1] = bv.y; acc[j][2] = bv.z; acc[j][3] = bv.w; }

    for (int kb = 0; kb < K; kb += 64) {
        __syncthreads();
        const float4* Wg = (const float4*)(W + (size_t)kb * 128);
        float4* Wsv = (float4*)Ws;
#pragma unroll
        for (int i = 0; i < 8; i++)
            Wsv[threadIdx.x + i * 256] = Wg[threadIdx.x + i * 256];
#pragma unroll
        for (int i = 0; i < 4; i++) {
            int idx = threadIdx.x + i * 256;
            int r = idx >> 4;
            int k4 = idx & 15;
            float4 v = make_float4(0.f, 0.f, 0.f, 0.f);
            if (r0 + r < N_)
                v = *(const float4*)(A + (size_t)(r0 + r) * K + kb + k4 * 4);
            *(float4*)&As[r * 64 + k4 * 4] = v;
        }
        __syncthreads();
#pragma unroll 4
        for (int k = 0; k < 64; k++) {
            float4 wv = *(const float4*)&Ws[k * 128 + c];
#pragma unroll
            for (int j = 0; j < 8; j++) {
                float a = As[(rowg + 8 * j) * 64 + k];
                acc[j][0] += a * wv.x;
                acc[j][1] += a * wv.y;
                acc[j][2] += a * wv.z;
                acc[j][3] += a * wv.w;
            }
        }
    }
#pragma unroll
    for (int j = 0; j < 8; j++) {
        int r = r0 + rowg + 8 * j;
        if (r < N_) {
            float4 o;
            o.x = fmaxf(acc[j][0], 0.f);
            o.y = fmaxf(acc[j][1], 0.f);
            o.z = fmaxf(acc[j][2], 0.f);
            o.w = fmaxf(acc[j][3], 0.f);
            *(float4*)(C + (size_t)r * 128 + c) = o;
        }
    }
}

// ---------------- pooling ----------------
__device__ __forceinline__ void pool_flush(int g, int lane, float4 s, float4 m, int cnt) {
    int base = g * 128 + lane * 4;
    atomicAdd(&g_psum[base + 0], s.x);
    atomicAdd(&g_psum[base + 1], s.y);
    atomicAdd(&g_psum[base + 2], s.z);
    atomicAdd(&g_psum[base + 3], s.w);
    atomicMax((int*)&g_pmax[base + 0], __float_as_int(m.x));
    atomicMax((int*)&g_pmax[base + 1], __float_as_int(m.y));
    atomicMax((int*)&g_pmax[base + 2], __float_as_int(m.z));
    atomicMax((int*)&g_pmax[base + 3], __float_as_int(m.w));
    if (lane == 0) atomicAdd(&g_pcnt[g], cnt);
}

__global__ void pool_kernel(const float* __restrict__ h, const int* __restrict__ batch) {
    int lane = threadIdx.x & 31;
    int warp = blockIdx.x * (blockDim.x >> 5) + (threadIdx.x >> 5);
    int n0 = warp * 64;
    if (n0 >= N_) return;
    int n1 = min(n0 + 64, N_);
    float4 s = make_float4(0.f, 0.f, 0.f, 0.f);
    float4 m = make_float4(0.f, 0.f, 0.f, 0.f);
    int cnt = 0;
    int cur = batch[n0];
    for (int n = n0; n < n1; n++) {
        int g = batch[n];
        if (g != cur) {
            pool_flush(cur, lane, s, m, cnt);
            s = make_float4(0.f, 0.f, 0.f, 0.f);
            m = make_float4(0.f, 0.f, 0.f, 0.f);
            cnt = 0; cur = g;
        }
        float4 v = ((const float4*)(h + (size_t)n * 128))[lane];
        s.x += v.x; s.y += v.y; s.z += v.z; s.w += v.w;
        m.x = fmaxf(m.x, v.x); m.y = fmaxf(m.y, v.y);
        m.z = fmaxf(m.z, v.z); m.w = fmaxf(m.w, v.w);
        cnt++;
    }
    pool_flush(cur, lane, s, m, cnt);
}

// ---------------- final MLP ----------------
__global__ void mlp_kernel(const float* __restrict__ Wp, const float* __restrict__ bp,
                           float* __restrict__ out) {
    __shared__ float hg[256];
    int g = blockIdx.x;
    int t = threadIdx.x;
    if (t < 128) {
        float cnt = (float)max(g_pcnt[g], 1);
        hg[t] = g_psum[g * 128 + t] / cnt;
    } else {
        hg[t] = g_pmax[g * 128 + (t - 128)];
    }
    __syncthreads();
    float acc = bp[t];
#pragma unroll 8
    for (int k = 0; k < 256; k++)
        acc += hg[k] * Wp[k * 256 + t];
    out[g * 256 + t] = fmaxf(acc, 0.f);
}

// ---------------- launch ----------------
extern "C" void kernel_launch(void* const* d_in, const int* in_sizes, int n_in,
                              void* d_out, int out_size) {
    const float* x     = (const float*)d_in[0];
    const int*   ei    = (const int*)d_in[1];
    const int*   batch = (const int*)d_in[2];
    const float* W_in  = (const float*)d_in[3];
    const float* b_in  = (const float*)d_in[4];
    const float* W1    = (const float*)d_in[5];
    const float* b1    = (const float*)d_in[6];
    const float* W2    = (const float*)d_in[7];
    const float* b2    = (const float*)d_in[8];
    const float* Wp    = (const float*)d_in[9];
    const float* bp    = (const float*)d_in[10];
    float* out = (float*)d_out;

    float *a2p, *h2p;
    cudaGetSymbolAddress((void**)&a2p, g_a2);
    cudaGetSymbolAddress((void**)&h2p, g_h2);

    const int SCAN_BLOCKS = (N_ + 511) / 512;   // 98

    zero_kernel<<<(N_ + 255) / 256, 256>>>();
    count_kernel<<<(E_ / 4 + 255) / 256, 256>>>(ei);
    scan1_kernel<<<SCAN_BLOCKS, 512>>>();
    scan23_kernel<<<(N_ + 255) / 256, 256>>>(SCAN_BLOCKS);
    fill_kernel<<<(E_ / 4 + 255) / 256, 256>>>(ei);

    prep_kernel<<<1, 128>>>(W_in, b_in, W1);

    // layer 1 fused: aggregate 6-dim + small GEMM + relu -> fp16 h1
    layer1_fused_kernel<<<(N_ + 7) / 8, 256>>>(x, b1);

    // layer 2
    spmm128_kernel<<<(N_ + 7) / 8, 256>>>(a2p);
    gemm128_kernel<<<(N_ + 63) / 64, 256>>>(a2p, W2, b2, h2p);

    // pooling + MLP
    {
        int warps = (N_ + 63) / 64;
        int blocks = (warps * 32 + 255) / 256;
        pool_kernel<<<blocks, 256>>>(h2p, batch);
    }
    mlp_kernel<<<G_, 256>>>(Wp, bp, out);
}

// round 7
// speedup vs baseline: 2.3348x; 1.6077x over previous
#include <cuda_runtime.h>
#include <cuda_fp16.h>
#include <mma.h>
#include <cstdint>

using namespace nvcuda;

#define N_  50000
#define E_  800000
#define G_  64
#define NPAD 50048   // 782 * 64

// ---------------- scratch (device globals; no allocation) ----------------
__device__ int    g_deg[N_];
__device__ int    g_rowptr[N_ + 1];
__device__ int    g_cursor[N_];
__device__ float  g_dinv[N_];
__device__ int    g_csr_src[E_];

__device__ int    g_scan[50176];        // 98 blocks * 512
__device__ int    g_bsum[128];
__device__ int    g_gstart[G_ + 1];

__device__ float  g_Wc[6 * 128];        // W_in @ W1
__device__ float  g_bW[128];            // b_in @ W1
__device__ __half g_W2h[128 * 128];     // fp16 W2

__device__ __half g_h1h[(size_t)N_ * 128];    // fp16 h1 (gather payload)
__device__ __half g_a2h[(size_t)NPAD * 128];  // fp16 aggregated features (tail rows stay 0)

__device__ float  g_psum[G_ * 128];
__device__ float  g_pmax[G_ * 128];

// ---------------- zero / reset ----------------
__global__ void zero_kernel() {
    int i = blockIdx.x * blockDim.x + threadIdx.x;
    if (i < N_) g_deg[i] = 0;
    if (i < G_ * 128) { g_psum[i] = 0.f; g_pmax[i] = 0.f; }
    if (i == 0) g_rowptr[N_] = E_;
}

// ---------------- degree count ----------------
__global__ void count_kernel(const int* __restrict__ ei) {
    int e4 = blockIdx.x * blockDim.x + threadIdx.x;
    if (e4 * 4 >= E_) return;
    int4 d = ((const int4*)(ei + E_))[e4];
    atomicAdd(&g_deg[d.x], 1);
    atomicAdd(&g_deg[d.y], 1);
    atomicAdd(&g_deg[d.z], 1);
    atomicAdd(&g_deg[d.w], 1);
}

// ---------------- scan stage 1 ----------------
__global__ void __launch_bounds__(512) scan1_kernel() {
    __shared__ int wsum[16];
    int t = threadIdx.x, lane = t & 31, wid = t >> 5;
    int i = blockIdx.x * 512 + t;
    int v = (i < N_) ? g_deg[i] : 0;
    int incl = v;
#pragma unroll
    for (int off = 1; off < 32; off <<= 1) {
        int n = __shfl_up_sync(0xffffffffu, incl, off);
        if (lane >= off) incl += n;
    }
    if (lane == 31) wsum[wid] = incl;
    __syncthreads();
    if (wid == 0) {
        int s = (lane < 16) ? wsum[lane] : 0;
#pragma unroll
        for (int off = 1; off < 16; off <<= 1) {
            int n = __shfl_up_sync(0xffffffffu, s, off);
            if (lane >= off) s += n;
        }
        if (lane < 16) wsum[lane] = s;
    }
    __syncthreads();
    if (wid > 0) incl += wsum[wid - 1];
    g_scan[blockIdx.x * 512 + t] = incl;
    if (t == 511) g_bsum[blockIdx.x] = incl;
    if (i < N_) g_dinv[i] = rsqrtf((float)(v + 1));
}

// ---------------- scan 2+3 ----------------
__global__ void scan23_kernel(int nblk) {
    __shared__ int sm[128];
    int t = threadIdx.x;
    if (t < 128) sm[t] = (t < nblk) ? g_bsum[t] : 0;
    __syncthreads();
    for (int off = 1; off < 128; off <<= 1) {
        int add = (t >= off && t < 128) ? sm[t - off] : 0;
        __syncthreads();
        if (t < 128) sm[t] += add;
        __syncthreads();
    }
    int i = blockIdx.x * 256 + t;
    if (i < N_) {
        int blk = i >> 9;
        int boff = blk ? sm[blk - 1] : 0;
        int excl = boff + g_scan[i] - g_deg[i];
        g_rowptr[i] = excl;
        g_cursor[i] = excl;
    }
}

// ---------------- CSR fill ----------------
__global__ void fill_kernel(const int* __restrict__ ei) {
    int e4 = blockIdx.x * blockDim.x + threadIdx.x;
    if (e4 * 4 >= E_) return;
    int4 s = ((const int4*)ei)[e4];
    int4 d = ((const int4*)(ei + E_))[e4];
    g_csr_src[atomicAdd(&g_cursor[d.x], 1)] = s.x;
    g_csr_src[atomicAdd(&g_cursor[d.y], 1)] = s.y;
    g_csr_src[atomicAdd(&g_cursor[d.z], 1)] = s.z;
    g_csr_src[atomicAdd(&g_cursor[d.w], 1)] = s.w;
}

// ---------------- graph starts via binary search (batch sorted) ----------------
__global__ void gstart_kernel(const int* __restrict__ batch) {
    int g = threadIdx.x;
    if (g > G_) return;
    int lo = 0, hi = N_;
    while (lo < hi) {
        int mid = (lo + hi) >> 1;
        if (batch[mid] < g) lo = mid + 1; else hi = mid;
    }
    g_gstart[g] = lo;
}

// ---------------- prep: Wc = W_in@W1, bW = b_in@W1 (block 0) + W2->fp16 (blocks 1..64) ----------------
__global__ void prep_kernel(const float* __restrict__ W_in,
                            const float* __restrict__ b_in,
                            const float* __restrict__ W1,
                            const float* __restrict__ W2) {
    int t = threadIdx.x;   // 128
    if (blockIdx.x == 0) {
        float acc[6] = {0.f, 0.f, 0.f, 0.f, 0.f, 0.f};
        float bb = 0.f;
        for (int k = 0; k < 64; k++) {
            float w1 = W1[k * 128 + t];
            bb += b_in[k] * w1;
#pragma unroll
            for (int r = 0; r < 6; r++)
                acc[r] += W_in[r * 64 + k] * w1;
        }
#pragma unroll
        for (int r = 0; r < 6; r++)
            g_Wc[r * 128 + t] = acc[r];
        g_bW[t] = bb;
    } else {
        int base = (blockIdx.x - 1) * 128;
        g_W2h[base + t] = __float2half(W2[base + t]);
    }
}

// ---------------- fused layer1: aggregate 6-dim + tiny GEMM + relu -> fp16 h1 ----------------
__global__ void __launch_bounds__(256) layer1_fused_kernel(const float* __restrict__ x,
                                                           const float* __restrict__ b1) {
    __shared__ float Wcs[6 * 128];
    __shared__ float bWs[128];
    __shared__ float b1s[128];
    int t = threadIdx.x;
    for (int i = t; i < 6 * 128; i += 256) Wcs[i] = g_Wc[i];
    if (t < 128) { bWs[t] = g_bW[t]; b1s[t] = b1[t]; }
    __syncthreads();

    int lane = t & 31;
    int node = blockIdx.x * 8 + (t >> 5);
    if (node >= N_) return;
    int beg = g_rowptr[node], end = g_rowptr[node + 1];

    float a0 = 0.f, a1 = 0.f, a2 = 0.f, a3 = 0.f, a4 = 0.f, a5 = 0.f, ws = 0.f;
    for (int e = beg + lane; e < end; e += 32) {
        int s = g_csr_src[e];
        float w = g_dinv[s];
        const float2* xr = (const float2*)(x + (size_t)s * 6);
        float2 p0 = xr[0], p1 = xr[1], p2 = xr[2];
        a0 += w * p0.x; a1 += w * p0.y;
        a2 += w * p1.x; a3 += w * p1.y;
        a4 += w * p2.x; a5 += w * p2.y;
        ws += w;
    }
#pragma unroll
    for (int off = 16; off; off >>= 1) {
        a0 += __shfl_xor_sync(0xffffffffu, a0, off);
        a1 += __shfl_xor_sync(0xffffffffu, a1, off);
        a2 += __shfl_xor_sync(0xffffffffu, a2, off);
        a3 += __shfl_xor_sync(0xffffffffu, a3, off);
        a4 += __shfl_xor_sync(0xffffffffu, a4, off);
        a5 += __shfl_xor_sync(0xffffffffu, a5, off);
        ws += __shfl_xor_sync(0xffffffffu, ws, off);
    }
    float di = g_dinv[node];
    const float2* xi = (const float2*)(x + (size_t)node * 6);
    float2 q0 = xi[0], q1 = xi[1], q2 = xi[2];
    float ax0 = di * (a0 + di * q0.x);
    float ax1 = di * (a1 + di * q0.y);
    float ax2 = di * (a2 + di * q1.x);
    float ax3 = di * (a3 + di * q1.y);
    float ax4 = di * (a4 + di * q2.x);
    float ax5 = di * (a5 + di * q2.y);
    float s   = di * (ws + di);

    int c = lane * 4;
    float o[4];
#pragma unroll
    for (int j = 0; j < 4; j++) {
        float acc = s * bWs[c + j] + b1s[c + j];
        acc += ax0 * Wcs[0 * 128 + c + j];
        acc += ax1 * Wcs[1 * 128 + c + j];
        acc += ax2 * Wcs[2 * 128 + c + j];
        acc += ax3 * Wcs[3 * 128 + c + j];
        acc += ax4 * Wcs[4 * 128 + c + j];
        acc += ax5 * Wcs[5 * 128 + c + j];
        o[j] = fmaxf(acc, 0.f);
    }
    __half2 h01 = __floats2half2_rn(o[0], o[1]);
    __half2 h23 = __floats2half2_rn(o[2], o[3]);
    uint2 u;
    u.x = *(unsigned int*)&h01;
    u.y = *(unsigned int*)&h23;
    ((uint2*)(g_h1h + (size_t)node * 128))[lane] = u;
}

// ---------------- spmm128: a2 = norm-aggregate(h1), fp16 in / fp32 acc / fp16 out ----------------
__global__ void spmm128_kernel() {
    int lane = threadIdx.x & 31;
    int node = blockIdx.x * (blockDim.x >> 5) + (threadIdx.x >> 5);
    if (node >= N_) return;
    int beg = g_rowptr[node], end = g_rowptr[node + 1];

    float4 acc = make_float4(0.f, 0.f, 0.f, 0.f);
    int e = beg;
    for (; e + 2 <= end; e += 2) {
        int s0 = g_csr_src[e];
        int s1 = g_csr_src[e + 1];
        float w0 = g_dinv[s0];
        float w1 = g_dinv[s1];
        uint2 u0 = ((const uint2*)(g_h1h + (size_t)s0 * 128))[lane];
        uint2 u1 = ((const uint2*)(g_h1h + (size_t)s1 * 128))[lane];
        float2 f0a = __half22float2(*(__half2*)&u0.x);
        float2 f0b = __half22float2(*(__half2*)&u0.y);
        float2 f1a = __half22float2(*(__half2*)&u1.x);
        float2 f1b = __half22float2(*(__half2*)&u1.y);
        acc.x += w0 * f0a.x + w1 * f1a.x;
        acc.y += w0 * f0a.y + w1 * f1a.y;
        acc.z += w0 * f0b.x + w1 * f1b.x;
        acc.w += w0 * f0b.y + w1 * f1b.y;
    }
    if (e < end) {
        int s0 = g_csr_src[e];
        float w0 = g_dinv[s0];
        uint2 u0 = ((const uint2*)(g_h1h + (size_t)s0 * 128))[lane];
        float2 f0a = __half22float2(*(__half2*)&u0.x);
        float2 f0b = __half22float2(*(__half2*)&u0.y);
        acc.x += w0 * f0a.x; acc.y += w0 * f0a.y;
        acc.z += w0 * f0b.x; acc.w += w0 * f0b.y;
    }
    float di = g_dinv[node];
    uint2 us = ((const uint2*)(g_h1h + (size_t)node * 128))[lane];
    float2 fsa = __half22float2(*(__half2*)&us.x);
    float2 fsb = __half22float2(*(__half2*)&us.y);
    acc.x = di * (acc.x + di * fsa.x);
    acc.y = di * (acc.y + di * fsa.y);
    acc.z = di * (acc.z + di * fsb.x);
    acc.w = di * (acc.w + di * fsb.y);
    __half2 h01 = __floats2half2_rn(acc.x, acc.y);
    __half2 h23 = __floats2half2_rn(acc.z, acc.w);
    uint2 u;
    u.x = *(unsigned int*)&h01;
    u.y = *(unsigned int*)&h23;
    ((uint2*)(g_a2h + (size_t)node * 128))[lane] = u;
}

// ---------------- fused tensor-core GEMM + bias + relu + pooling ----------------
// h2_tile[64,128] = relu(a2[64 rows,128] @ W2[128,128] + b2); pool directly.
#define SM_W_OFF   0                        // Wsh: 64 x 136 half  (17408 B)
#define SM_A_OFF   17408                    // Ash: 64 x 72  half  ( 9216 B)
#define SM_O_OFF   0                        // Osh: 64 x 128 float (32768 B) reuse
#define SM_BYTES   33792

__global__ void __launch_bounds__(256) gemmpool_kernel(const int* __restrict__ batch,
                                                       const float* __restrict__ b2) {
    __shared__ __align__(16) char smraw[SM_BYTES];
    __shared__ float b2s[128];
    __shared__ int   sbatch[64];
    __half* Wsh = (__half*)(smraw + SM_W_OFF);   // ld 136
    __half* Ash = (__half*)(smraw + SM_A_OFF);   // ld 72
    float*  Osh = (float*) (smraw + SM_O_OFF);   // ld 128

    int t = threadIdx.x;
    int r0 = blockIdx.x * 64;

    if (t < 128) b2s[t] = b2[t];
    if (t < 64)  sbatch[t] = (r0 + t < N_) ? batch[r0 + t] : G_ - 1;

    int wid  = t >> 5;
    int wm   = wid & 1;          // 0..1  -> rows wm*32
    int wn   = wid >> 1;         // 0..3  -> cols wn*32

    wmma::fragment<wmma::accumulator, 16, 16, 16, float> accf[2][2];
#pragma unroll
    for (int i = 0; i < 2; i++)
#pragma unroll
        for (int j = 0; j < 2; j++)
            wmma::fill_fragment(accf[i][j], 0.f);

    for (int kb = 0; kb < 128; kb += 64) {
        __syncthreads();
        // load W chunk: rows kb..kb+63 of W2h [128][128] -> Wsh[64][136]
        {
            const uint2* Wg = (const uint2*)(g_W2h + (size_t)kb * 128);
#pragma unroll
            for (int i = 0; i < 8; i++) {
                int idx = t + i * 256;        // uint2 index, 32 per row
                int r = idx >> 5, c = idx & 31;
                uint2 v = Wg[idx];
                *(uint2*)(Wsh + r * 136 + c * 4) = v;
            }
        }
        // load A chunk: 64 rows x cols kb..kb+63 -> Ash[64][72]
        {
#pragma unroll
            for (int i = 0; i < 4; i++) {
                int idx = t + i * 256;        // uint2 index, 16 per row
                int r = idx >> 4, c = idx & 15;
                uint2 v = *(const uint2*)(g_a2h + (size_t)(r0 + r) * 128 + kb + c * 4);
                *(uint2*)(Ash + r * 72 + c * 4) = v;
            }
        }
        __syncthreads();
#pragma unroll
        for (int kk = 0; kk < 64; kk += 16) {
            wmma::fragment<wmma::matrix_a, 16, 16, 16, __half, wmma::row_major> af[2];
            wmma::fragment<wmma::matrix_b, 16, 16, 16, __half, wmma::row_major> bf[2];
#pragma unroll
            for (int i = 0; i < 2; i++)
                wmma::load_matrix_sync(af[i], Ash + (wm * 32 + i * 16) * 72 + kk, 72);
#pragma unroll
            for (int j = 0; j < 2; j++)
                wmma::load_matrix_sync(bf[j], Wsh + kk * 136 + wn * 32 + j * 16, 136);
#pragma unroll
            for (int i = 0; i < 2; i++)
#pragma unroll
                for (int j = 0; j < 2; j++)
                    wmma::mma_sync(accf[i][j], af[i], bf[j], accf[i][j]);
        }
    }

    __syncthreads();   // done reading Ash/Wsh; reuse as Osh
#pragma unroll
    for (int i = 0; i < 2; i++)
#pragma unroll
        for (int j = 0; j < 2; j++)
            wmma::store_matrix_sync(Osh + (wm * 32 + i * 16) * 128 + wn * 32 + j * 16,
                                    accf[i][j], 128, wmma::mem_row_major);
    __syncthreads();

    // pooling: thread t < 128 owns column t; run-length reduce over 64 sorted rows
    if (t < 128) {
        float s = 0.f, m = 0.f;
        int cur = sbatch[0];
        int rmax = min(64, N_ - r0);
        for (int r = 0; r < rmax; r++) {
            int g = sbatch[r];
            if (g != cur) {
                atomicAdd(&g_psum[cur * 128 + t], s);
                atomicMax((int*)&g_pmax[cur * 128 + t], __float_as_int(m));
                s = 0.f; m = 0.f; cur = g;
            }
            float v = fmaxf(Osh[r * 128 + t] + b2s[t], 0.f);
            s += v;
            m = fmaxf(m, v);
        }
        atomicAdd(&g_psum[cur * 128 + t], s);
        atomicMax((int*)&g_pmax[cur * 128 + t], __float_as_int(m));
    }
}

// ---------------- final MLP ----------------
__global__ void mlp_kernel(const float* __restrict__ Wp, const float* __restrict__ bp,
                           float* __restrict__ out) {
    __shared__ float hg[256];
    int g = blockIdx.x;
    int t = threadIdx.x;
    if (t < 128) {
        float cnt = (float)max(g_gstart[g + 1] - g_gstart[g], 1);
        hg[t] = g_psum[g * 128 + t] / cnt;
    } else {
        hg[t] = g_pmax[g * 128 + (t - 128)];
    }
    __syncthreads();
    float acc = bp[t];
#pragma unroll 8
    for (int k = 0; k < 256; k++)
        acc += hg[k] * Wp[k * 256 + t];
    out[g * 256 + t] = fmaxf(acc, 0.f);
}

// ---------------- launch ----------------
extern "C" void kernel_launch(void* const* d_in, const int* in_sizes, int n_in,
                              void* d_out, int out_size) {
    const float* x     = (const float*)d_in[0];
    const int*   ei    = (const int*)d_in[1];
    const int*   batch = (const int*)d_in[2];
    const float* W_in  = (const float*)d_in[3];
    const float* b_in  = (const float*)d_in[4];
    const float* W1    = (const float*)d_in[5];
    const float* b1    = (const float*)d_in[6];
    const float* W2    = (const float*)d_in[7];
    const float* b2    = (const float*)d_in[8];
    const float* Wp    = (const float*)d_in[9];
    const float* bp    = (const float*)d_in[10];
    float* out = (float*)d_out;

    const int SCAN_BLOCKS = (N_ + 511) / 512;   // 98

    zero_kernel<<<(N_ + 255) / 256, 256>>>();
    count_kernel<<<(E_ / 4 + 255) / 256, 256>>>(ei);
    scan1_kernel<<<SCAN_BLOCKS, 512>>>();
    scan23_kernel<<<(N_ + 255) / 256, 256>>>(SCAN_BLOCKS);
    fill_kernel<<<(E_ / 4 + 255) / 256, 256>>>(ei);
    gstart_kernel<<<1, 128>>>(batch);
    prep_kernel<<<129, 128>>>(W_in, b_in, W1, W2);

    layer1_fused_kernel<<<(N_ + 7) / 8, 256>>>(x, b1);
    spmm128_kernel<<<(N_ + 7) / 8, 256>>>();
    gemmpool_kernel<<<NPAD / 64, 256>>>(batch, b2);
    mlp_kernel<<<G_, 256>>>(Wp, bp, out);
}

// round 8
// speedup vs baseline: 2.4101x; 1.0323x over previous
#include <cuda_runtime.h>
#include <cuda_fp16.h>
#include <mma.h>
#include <cstdint>

using namespace nvcuda;

#define N_  50000
#define E_  800000
#define G_  64

// ---------------- scratch (device globals; no allocation) ----------------
__device__ int    g_deg[N_];
__device__ int    g_rowptr[N_ + 1];
__device__ int    g_cursor[N_];
__device__ float  g_dinv[N_];
__device__ int    g_csr_src[E_];

__device__ int    g_scan[50176];        // 98 blocks * 512
__device__ int    g_bsum[128];
__device__ int    g_gstart[G_ + 1];

__device__ float  g_Wc[6 * 128];        // W_in @ W1
__device__ float  g_bW[128];            // b_in @ W1
__device__ __half g_W2h[128 * 128];     // fp16 W2

__device__ __half g_h1h[(size_t)N_ * 128];    // fp16 h1 (gather payload)

__device__ float  g_psum[G_ * 128];
__device__ float  g_pmax[G_ * 128];

// ---------------- setup: zero (blocks 0..195) + gstart (196) + prep (197..325) ----------------
__global__ void setup_kernel(const int* __restrict__ batch,
                             const float* __restrict__ W_in,
                             const float* __restrict__ b_in,
                             const float* __restrict__ W1,
                             const float* __restrict__ W2) {
    int blk = blockIdx.x;
    int t = threadIdx.x;
    if (blk < 196) {
        int i = blk * 256 + t;
        if (i < N_) g_deg[i] = 0;
        if (i < G_ * 128) { g_psum[i] = 0.f; g_pmax[i] = 0.f; }
        if (i == 0) g_rowptr[N_] = E_;
    } else if (blk == 196) {
        if (t <= G_) {
            int lo = 0, hi = N_;
            while (lo < hi) {
                int mid = (lo + hi) >> 1;
                if (batch[mid] < t) lo = mid + 1; else hi = mid;
            }
            g_gstart[t] = lo;
        }
    } else if (blk == 197) {
        if (t < 128) {
            float acc[6] = {0.f, 0.f, 0.f, 0.f, 0.f, 0.f};
            float bb = 0.f;
            for (int k = 0; k < 64; k++) {
                float w1 = W1[k * 128 + t];
                bb += b_in[k] * w1;
#pragma unroll
                for (int r = 0; r < 6; r++)
                    acc[r] += W_in[r * 64 + k] * w1;
            }
#pragma unroll
            for (int r = 0; r < 6; r++)
                g_Wc[r * 128 + t] = acc[r];
            g_bW[t] = bb;
        }
    } else {
        if (t < 128) {
            int base = (blk - 198) * 128;
            g_W2h[base + t] = __float2half(W2[base + t]);
        }
    }
}

// ---------------- degree count ----------------
__global__ void count_kernel(const int* __restrict__ ei) {
    int e4 = blockIdx.x * blockDim.x + threadIdx.x;
    if (e4 * 4 >= E_) return;
    int4 d = ((const int4*)(ei + E_))[e4];
    atomicAdd(&g_deg[d.x], 1);
    atomicAdd(&g_deg[d.y], 1);
    atomicAdd(&g_deg[d.z], 1);
    atomicAdd(&g_deg[d.w], 1);
}

// ---------------- scan stage 1 ----------------
__global__ void __launch_bounds__(512) scan1_kernel() {
    __shared__ int wsum[16];
    int t = threadIdx.x, lane = t & 31, wid = t >> 5;
    int i = blockIdx.x * 512 + t;
    int v = (i < N_) ? g_deg[i] : 0;
    int incl = v;
#pragma unroll
    for (int off = 1; off < 32; off <<= 1) {
        int n = __shfl_up_sync(0xffffffffu, incl, off);
        if (lane >= off) incl += n;
    }
    if (lane == 31) wsum[wid] = incl;
    __syncthreads();
    if (wid == 0) {
        int s = (lane < 16) ? wsum[lane] : 0;
#pragma unroll
        for (int off = 1; off < 16; off <<= 1) {
            int n = __shfl_up_sync(0xffffffffu, s, off);
            if (lane >= off) s += n;
        }
        if (lane < 16) wsum[lane] = s;
    }
    __syncthreads();
    if (wid > 0) incl += wsum[wid - 1];
    g_scan[blockIdx.x * 512 + t] = incl;
    if (t == 511) g_bsum[blockIdx.x] = incl;
    if (i < N_) g_dinv[i] = rsqrtf((float)(v + 1));
}

// ---------------- scan 2+3 (warp-shuffle block-sum scan, 1 barrier) ----------------
__global__ void scan23_kernel(int nblk) {
    __shared__ int warptot[4];
    __shared__ int pref[128];
    int t = threadIdx.x;
    if (t < 128) {
        int lane = t & 31, w = t >> 5;
        int v = (t < nblk) ? g_bsum[t] : 0;
        int incl = v;
#pragma unroll
        for (int off = 1; off < 32; off <<= 1) {
            int n = __shfl_up_sync(0xffffffffu, incl, off);
            if (lane >= off) incl += n;
        }
        if (lane == 31) warptot[w] = incl;
        pref[t] = incl;
    }
    __syncthreads();
    int i = blockIdx.x * 256 + t;
    if (i < N_) {
        int blk = i >> 9;
        int boff = 0;
        if (blk > 0) {
            int w = (blk - 1) >> 5;
            boff = pref[blk - 1];
            for (int j = 0; j < w; j++) boff += warptot[j];
        }
        int excl = boff + g_scan[i] - g_deg[i];
        g_rowptr[i] = excl;
        g_cursor[i] = excl;
    }
}

// ---------------- CSR fill ----------------
__global__ void fill_kernel(const int* __restrict__ ei) {
    int e4 = blockIdx.x * blockDim.x + threadIdx.x;
    if (e4 * 4 >= E_) return;
    int4 s = ((const int4*)ei)[e4];
    int4 d = ((const int4*)(ei + E_))[e4];
    g_csr_src[atomicAdd(&g_cursor[d.x], 1)] = s.x;
    g_csr_src[atomicAdd(&g_cursor[d.y], 1)] = s.y;
    g_csr_src[atomicAdd(&g_cursor[d.z], 1)] = s.z;
    g_csr_src[atomicAdd(&g_cursor[d.w], 1)] = s.w;
}

// ---------------- fused layer1: aggregate 6-dim + tiny GEMM + relu -> fp16 h1 ----------------
__global__ void __launch_bounds__(256) layer1_fused_kernel(const float* __restrict__ x,
                                                           const float* __restrict__ b1) {
    __shared__ float Wcs[6 * 128];
    __shared__ float bWs[128];
    __shared__ float b1s[128];
    int t = threadIdx.x;
    for (int i = t; i < 6 * 128; i += 256) Wcs[i] = g_Wc[i];
    if (t < 128) { bWs[t] = g_bW[t]; b1s[t] = b1[t]; }
    __syncthreads();

    int lane = t & 31;
    int node = blockIdx.x * 8 + (t >> 5);
    if (node >= N_) return;
    int beg = g_rowptr[node], end = g_rowptr[node + 1];

    float a0 = 0.f, a1 = 0.f, a2 = 0.f, a3 = 0.f, a4 = 0.f, a5 = 0.f, ws = 0.f;
    for (int e = beg + lane; e < end; e += 32) {
        int s = g_csr_src[e];
        float w = g_dinv[s];
        const float2* xr = (const float2*)(x + (size_t)s * 6);
        float2 p0 = xr[0], p1 = xr[1], p2 = xr[2];
        a0 += w * p0.x; a1 += w * p0.y;
        a2 += w * p1.x; a3 += w * p1.y;
        a4 += w * p2.x; a5 += w * p2.y;
        ws += w;
    }
#pragma unroll
    for (int off = 16; off; off >>= 1) {
        a0 += __shfl_xor_sync(0xffffffffu, a0, off);
        a1 += __shfl_xor_sync(0xffffffffu, a1, off);
        a2 += __shfl_xor_sync(0xffffffffu, a2, off);
        a3 += __shfl_xor_sync(0xffffffffu, a3, off);
        a4 += __shfl_xor_sync(0xffffffffu, a4, off);
        a5 += __shfl_xor_sync(0xffffffffu, a5, off);
        ws += __shfl_xor_sync(0xffffffffu, ws, off);
    }
    float di = g_dinv[node];
    const float2* xi = (const float2*)(x + (size_t)node * 6);
    float2 q0 = xi[0], q1 = xi[1], q2 = xi[2];
    float ax0 = di * (a0 + di * q0.x);
    float ax1 = di * (a1 + di * q0.y);
    float ax2 = di * (a2 + di * q1.x);
    float ax3 = di * (a3 + di * q1.y);
    float ax4 = di * (a4 + di * q2.x);
    float ax5 = di * (a5 + di * q2.y);
    float s   = di * (ws + di);

    int c = lane * 4;
    float o[4];
#pragma unroll
    for (int j = 0; j < 4; j++) {
        float acc = s * bWs[c + j] + b1s[c + j];
        acc += ax0 * Wcs[0 * 128 + c + j];
        acc += ax1 * Wcs[1 * 128 + c + j];
        acc += ax2 * Wcs[2 * 128 + c + j];
        acc += ax3 * Wcs[3 * 128 + c + j];
        acc += ax4 * Wcs[4 * 128 + c + j];
        acc += ax5 * Wcs[5 * 128 + c + j];
        o[j] = fmaxf(acc, 0.f);
    }
    __half2 h01 = __floats2half2_rn(o[0], o[1]);
    __half2 h23 = __floats2half2_rn(o[2], o[3]);
    uint2 u;
    u.x = *(unsigned int*)&h01;
    u.y = *(unsigned int*)&h23;
    ((uint2*)(g_h1h + (size_t)node * 128))[lane] = u;
}

// ---------------- fused: spmm128 aggregation -> smem -> HMMA GEMM + bias/relu + pooling ----------------
// Block handles 64 nodes. Each of 8 warps aggregates 8 nodes into Ash (fp16),
// then wmma GEMM vs W2 (two 64-row K chunks), then run-length pooling.
#define FLD 136
#define SM_A_OFF 0                       // Ash: 64 x 136 half = 17408 B
#define SM_W_OFF 17408                   // Wsh: 64 x 136 half = 17408 B
#define SM_BYTES 34816                   // Osh (64x128 f32 = 32768 B) reuses whole region

__global__ void __launch_bounds__(256) spgemmpool_kernel(const int* __restrict__ batch,
                                                         const float* __restrict__ b2) {
    __shared__ __align__(16) char smraw[SM_BYTES];
    __shared__ float b2s[128];
    __shared__ int   sbatch[64];
    __half* Ash = (__half*)(smraw + SM_A_OFF);
    __half* Wsh = (__half*)(smraw + SM_W_OFF);
    float*  Osh = (float*)smraw;

    int t = threadIdx.x;
    int r0 = blockIdx.x * 64;
    int lane = t & 31;
    int w = t >> 5;

    if (t < 128) b2s[t] = b2[t];
    if (t < 64)  sbatch[t] = (r0 + t < N_) ? batch[r0 + t] : G_ - 1;

    // ---- aggregation: warp w handles local rows w, w+8, ..., w+56 ----
    for (int rr = w; rr < 64; rr += 8) {
        int node = r0 + rr;
        float4 acc = make_float4(0.f, 0.f, 0.f, 0.f);
        if (node < N_) {
            int beg = g_rowptr[node], end = g_rowptr[node + 1];
            int e = beg;
            for (; e + 2 <= end; e += 2) {
                int s0 = g_csr_src[e];
                int s1 = g_csr_src[e + 1];
                float w0 = g_dinv[s0];
                float w1 = g_dinv[s1];
                uint2 u0 = ((const uint2*)(g_h1h + (size_t)s0 * 128))[lane];
                uint2 u1 = ((const uint2*)(g_h1h + (size_t)s1 * 128))[lane];
                float2 f0a = __half22float2(*(__half2*)&u0.x);
                float2 f0b = __half22float2(*(__half2*)&u0.y);
                float2 f1a = __half22float2(*(__half2*)&u1.x);
                float2 f1b = __half22float2(*(__half2*)&u1.y);
                acc.x += w0 * f0a.x + w1 * f1a.x;
                acc.y += w0 * f0a.y + w1 * f1a.y;
                acc.z += w0 * f0b.x + w1 * f1b.x;
                acc.w += w0 * f0b.y + w1 * f1b.y;
            }
            if (e < end) {
                int s0 = g_csr_src[e];
                float w0 = g_dinv[s0];
                uint2 u0 = ((const uint2*)(g_h1h + (size_t)s0 * 128))[lane];
                float2 f0a = __half22float2(*(__half2*)&u0.x);
                float2 f0b = __half22float2(*(__half2*)&u0.y);
                acc.x += w0 * f0a.x; acc.y += w0 * f0a.y;
                acc.z += w0 * f0b.x; acc.w += w0 * f0b.y;
            }
            float di = g_dinv[node];
            uint2 us = ((const uint2*)(g_h1h + (size_t)node * 128))[lane];
            float2 fsa = __half22float2(*(__half2*)&us.x);
            float2 fsb = __half22float2(*(__half2*)&us.y);
            acc.x = di * (acc.x + di * fsa.x);
            acc.y = di * (acc.y + di * fsa.y);
            acc.z = di * (acc.z + di * fsb.x);
            acc.w = di * (acc.w + di * fsb.y);
        }
        __half2 h01 = __floats2half2_rn(acc.x, acc.y);
        __half2 h23 = __floats2half2_rn(acc.z, acc.w);
        uint2 u;
        u.x = *(unsigned int*)&h01;
        u.y = *(unsigned int*)&h23;
        *(uint2*)(Ash + rr * FLD + lane * 4) = u;
    }

    // ---- GEMM: Osh[64,128] = Ash[64,128] @ W2[128,128], fp32 acc ----
    int wm = w & 1;     // row group (0..1) * 32
    int wn = w >> 1;    // col group (0..3) * 32
    wmma::fragment<wmma::accumulator, 16, 16, 16, float> accf[2][2];
#pragma unroll
    for (int i = 0; i < 2; i++)
#pragma unroll
        for (int j = 0; j < 2; j++)
            wmma::fill_fragment(accf[i][j], 0.f);

    for (int kb = 0; kb < 128; kb += 64) {
        __syncthreads();    // Ash writes done (iter 0) / Wsh reads done (iter 1)
        {
            const uint2* Wg = (const uint2*)(g_W2h + (size_t)kb * 128);
#pragma unroll
            for (int i = 0; i < 8; i++) {
                int idx = t + i * 256;        // 2048 uint2: 64 rows x 32
                int r = idx >> 5, c = idx & 31;
                *(uint2*)(Wsh + r * FLD + c * 4) = Wg[idx];
            }
        }
        __syncthreads();
#pragma unroll
        for (int kk = 0; kk < 64; kk += 16) {
            wmma::fragment<wmma::matrix_a, 16, 16, 16, __half, wmma::row_major> af[2];
            wmma::fragment<wmma::matrix_b, 16, 16, 16, __half, wmma::row_major> bf[2];
#pragma unroll
            for (int i = 0; i < 2; i++)
                wmma::load_matrix_sync(af[i], Ash + (wm * 32 + i * 16) * FLD + kb + kk, FLD);
#pragma unroll
            for (int j = 0; j < 2; j++)
                wmma::load_matrix_sync(bf[j], Wsh + kk * FLD + wn * 32 + j * 16, FLD);
#pragma unroll
            for (int i = 0; i < 2; i++)
#pragma unroll
                for (int j = 0; j < 2; j++)
                    wmma::mma_sync(accf[i][j], af[i], bf[j], accf[i][j]);
        }
    }

    __syncthreads();   // all smem reads done; reuse as Osh
#pragma unroll
    for (int i = 0; i < 2; i++)
#pragma unroll
        for (int j = 0; j < 2; j++)
            wmma::store_matrix_sync(Osh + (wm * 32 + i * 16) * 128 + wn * 32 + j * 16,
                                    accf[i][j], 128, wmma::mem_row_major);
    __syncthreads();

    // ---- pooling: thread t < 128 owns column t; run-length over sorted rows ----
    if (t < 128) {
        float s = 0.f, m = 0.f;
        int cur = sbatch[0];
        int rmax = min(64, N_ - r0);
        for (int r = 0; r < rmax; r++) {
            int g = sbatch[r];
            if (g != cur) {
                atomicAdd(&g_psum[cur * 128 + t], s);
                atomicMax((int*)&g_pmax[cur * 128 + t], __float_as_int(m));
                s = 0.f; m = 0.f; cur = g;
            }
            float v = fmaxf(Osh[r * 128 + t] + b2s[t], 0.f);
            s += v;
            m = fmaxf(m, v);
        }
        atomicAdd(&g_psum[cur * 128 + t], s);
        atomicMax((int*)&g_pmax[cur * 128 + t], __float_as_int(m));
    }
}

// ---------------- final MLP ----------------
__global__ void mlp_kernel(const float* __restrict__ Wp, const float* __restrict__ bp,
                           float* __restrict__ out) {
    __shared__ float hg[256];
    int g = blockIdx.x;
    int t = threadIdx.x;
    if (t < 128) {
        float cnt = (float)max(g_gstart[g + 1] - g_gstart[g], 1);
        hg[t] = g_psum[g * 128 + t] / cnt;
    } else {
        hg[t] = g_pmax[g * 128 + (t - 128)];
    }
    __syncthreads();
    float acc = bp[t];
#pragma unroll 8
    for (int k = 0; k < 256; k++)
        acc += hg[k] * Wp[k * 256 + t];
    out[g * 256 + t] = fmaxf(acc, 0.f);
}

// ---------------- launch ----------------
extern "C" void kernel_launch(void* const* d_in, const int* in_sizes, int n_in,
                              void* d_out, int out_size) {
    const float* x     = (const float*)d_in[0];
    const int*   ei    = (const int*)d_in[1];
    const int*   batch = (const int*)d_in[2];
    const float* W_in  = (const float*)d_in[3];
    const float* b_in  = (const float*)d_in[4];
    const float* W1    = (const float*)d_in[5];
    const float* b1    = (const float*)d_in[6];
    const float* W2    = (const float*)d_in[7];
    const float* b2    = (const float*)d_in[8];
    const float* Wp    = (const float*)d_in[9];
    const float* bp    = (const float*)d_in[10];
    float* out = (float*)d_out;

    const int SCAN_BLOCKS = (N_ + 511) / 512;   // 98

    setup_kernel<<<326, 256>>>(batch, W_in, b_in, W1, W2);
    count_kernel<<<(E_ / 4 + 255) / 256, 256>>>(ei);
    scan1_kernel<<<SCAN_BLOCKS, 512>>>();
    scan23_kernel<<<(N_ + 255) / 256, 256>>>(SCAN_BLOCKS);
    fill_kernel<<<(E_ / 4 + 255) / 256, 256>>>(ei);

    layer1_fused_kernel<<<(N_ + 7) / 8, 256>>>(x, b1);
    spgemmpool_kernel<<<(N_ + 63) / 64, 256>>>(batch, b2);
    mlp_kernel<<<G_, 256>>>(Wp, bp, out);
}